// round 6
// baseline (speedup 1.0000x reference)
#include <cuda_runtime.h>
#include <cstdint>

// Problem constants (fixed by the reference setup_inputs)
constexpr int B = 256;
constexpr int T = 30000;
constexpr int C = 3;

constexpr int L = 1200;           // output chunk length; T/L = 25 chunks
constexpr int W = 336;            // warm-up steps; (L+W) = 1536 = 6*256 exactly
constexpr int NCHUNK = T / L;     // 25

constexpr float ALPHA = 0.939f;
constexpr float CFF   = 3.0f;
constexpr float EPS   = 1e-10f;

__host__ __device__ constexpr double dpow(double a, int n) {
    double v = 1.0;
    for (int i = 0; i < n; ++i) v *= a;
    return v;
}
__device__ constexpr float APJ[8] = {   // alpha^(j+1), j = 0..7
    (float)dpow(0.939, 1), (float)dpow(0.939, 2), (float)dpow(0.939, 3), (float)dpow(0.939, 4),
    (float)dpow(0.939, 5), (float)dpow(0.939, 6), (float)dpow(0.939, 7), (float)dpow(0.939, 8)
};
__device__ constexpr float SCOEF[5] = { // alpha^(8 * 2^st), st = 0..4
    (float)dpow(0.939, 8), (float)dpow(0.939, 16), (float)dpow(0.939, 32),
    (float)dpow(0.939, 64), (float)dpow(0.939, 128)
};

#define FULLMASK 0xffffffffu

// Per-warp smem tile: 32 rows x 28 floats (24 data + 4 pad) = 3584 B.
// Row stride 112 B -> 28 words: 28*l mod 32 distinct over any 8-lane phase
// -> conflict-free LDS.128/STS.128 on rows.
constexpr int ROW_F = 28;                 // padded row length in floats
constexpr int WARP_TILE_F = 32 * ROW_F;   // 896 floats per warp

__global__ __launch_bounds__(128)
void char_scan_kernel(const float* __restrict__ in, float* __restrict__ out) {
    __shared__ float sm_all[4][WARP_TILE_F];

    const int gwarp = (blockIdx.x * blockDim.x + threadIdx.x) >> 5;
    const int lane  = threadIdx.x & 31;
    if (gwarp >= B * NCHUNK) return;

    float* const sm = sm_all[(threadIdx.x >> 5)];

    const int b  = gwarp / NCHUNK;
    const int k  = gwarp % NCHUNK;
    const int t0 = k * L;                  // first stored timestep
    const int ts = (k == 0) ? 0 : t0 - W;  // first scanned timestep
    const int tend = t0 + L;               // exclusive store bound

    const float* __restrict__ base  = in  + (size_t)b * T * C;
    float* __restrict__       obase = out + (size_t)b * T * C;

    // cross-round carries
    float carry_d[3] = {0.f, 0.f, 0.f};
    float carry_r[3];
    if (ts == 0) {
        carry_r[0] = 0.f; carry_r[1] = 0.f; carry_r[2] = 0.f;
    } else {
        carry_r[0] = base[(size_t)(ts - 1) * 3 + 0];
        carry_r[1] = base[(size_t)(ts - 1) * 3 + 1];
        carry_r[2] = base[(size_t)(ts - 1) * 3 + 2];
    }

    const int nrounds = (tend - ts + 255) >> 8;   // 256 timesteps per round
    // All rounds' loads are fully inside [0,T): interior/last chunks cover
    // exactly ts..tend; chunk 0 covers 0..1280 < T. No load guards needed.

    const int g0lo = t0 * 3;     // store-valid float range [g0lo, g0hi)
    const int g0hi = tend * 3;

    for (int rd = 0; rd < nrounds; ++rd) {
        const int tb = ts + rd * 256;             // round base timestep (mult of 8)
        const int fb = tb * 3;                    // round base float index (16B aligned)

        // ---- 1) coalesced global load: 6 x float4, lane-contiguous ----
        float4 v[6];
        const float4* p4 = reinterpret_cast<const float4*>(base + fb);
        #pragma unroll
        for (int q = 0; q < 6; ++q) v[q] = p4[q * 32 + lane];

        // ---- 2) transposed write into padded smem ----
        // tile float g -> smem byte addr g*4 + (g/24)*16 (= row*112 + (g%24)*4)
        #pragma unroll
        for (int q = 0; q < 6; ++q) {
            const int g = (q * 32 + lane) * 4;
            float* dst = (float*)((char*)sm + g * 4 + (g / 24) * 16);
            *reinterpret_cast<float4*>(dst) = v[q];
        }
        __syncwarp();

        // ---- 3) read own row: 24 floats = timesteps tb+8*lane .. +7, ch-major ----
        float r[24];
        {
            const float* row = (const float*)((char*)sm + lane * 112);
            #pragma unroll
            for (int q = 0; q < 6; ++q) {
                float4 u = reinterpret_cast<const float4*>(row)[q];
                r[q * 4 + 0] = u.x; r[q * 4 + 1] = u.y;
                r[q * 4 + 2] = u.z; r[q * 4 + 3] = u.w;
            }
        }

        float y[24];

        #pragma unroll
        for (int c = 0; c < 3; ++c) {
            float rp = __shfl_up_sync(FULLMASK, r[21 + c], 1);
            if (lane == 0) rp = carry_r[c];

            // local serial scan over 8 steps; lane 0 folds in carry_d
            float s[8];
            float u0 = (r[c] - rp) + EPS;
            s[0] = (lane == 0) ? fmaf(ALPHA, carry_d[c], u0) : u0;
            #pragma unroll
            for (int j = 1; j < 8; ++j) {
                float uj = (r[j * 3 + c] - r[(j - 1) * 3 + c]) + EPS;
                s[j] = fmaf(ALPHA, s[j - 1], uj);
            }

            // Kogge-Stone over lane aggregates, ratio alpha^8
            float p = s[7];
            #pragma unroll
            for (int st = 0; st < 5; ++st) {
                const int dlt = 1 << st;
                float tshf = __shfl_up_sync(FULLMASK, p, dlt);
                if (lane >= dlt) p = fmaf(SCOEF[st], tshf, p);
            }

            float inc = __shfl_up_sync(FULLMASK, p, 1);
            float dprev;
            if (lane == 0) { inc = 0.f; dprev = carry_d[c]; }
            else           { dprev = inc; }

            #pragma unroll
            for (int j = 0; j < 8; ++j) {
                float d    = fmaf(APJ[j], inc, s[j]);
                float diff = d - dprev;
                y[j * 3 + c] = fmaf(d, d, CFF * (diff * diff));
                dprev = d;
            }

            carry_d[c] = __shfl_sync(FULLMASK, p, 31);
            carry_r[c] = __shfl_sync(FULLMASK, r[21 + c], 31);
        }

        // ---- 4) write own row back (no cross-lane hazard vs step 3) ----
        {
            float* row = (float*)((char*)sm + lane * 112);
            #pragma unroll
            for (int q = 0; q < 6; ++q) {
                float4 u;
                u.x = y[q * 4 + 0]; u.y = y[q * 4 + 1];
                u.z = y[q * 4 + 2]; u.w = y[q * 4 + 3];
                reinterpret_cast<float4*>(row)[q] = u;
            }
        }
        __syncwarp();

        // ---- 5) coalesced read + guarded coalesced global store ----
        float4* o4 = reinterpret_cast<float4*>(obase + fb);
        #pragma unroll
        for (int q = 0; q < 6; ++q) {
            const int g  = (q * 32 + lane) * 4;   // tile-local float index
            const int gf = fb + g;                // global float index
            const float* src = (const float*)((char*)sm + g * 4 + (g / 24) * 16);
            float4 w = *reinterpret_cast<const float4*>(src);
            if (gf >= g0lo && gf < g0hi) o4[q * 32 + lane] = w;
        }
        __syncwarp();   // protect smem before next round's writes
    }
}

extern "C" void kernel_launch(void* const* d_in, const int* in_sizes, int n_in,
                              void* d_out, int out_size) {
    (void)in_sizes; (void)n_in; (void)out_size;
    const float* in = (const float*)d_in[0];
    float* out = (float*)d_out;

    const int total_warps   = B * NCHUNK;          // 6400
    const int threads       = 128;                 // 4 warps / block
    const int warps_per_blk = threads / 32;
    const int blocks        = (total_warps + warps_per_blk - 1) / warps_per_blk;  // 1600

    char_scan_kernel<<<blocks, threads>>>(in, out);
}

// round 7
// speedup vs baseline: 1.0982x; 1.0982x over previous
#include <cuda_runtime.h>
#include <cstdint>

// Problem constants (fixed by the reference setup_inputs)
constexpr int B = 256;
constexpr int T = 30000;
constexpr int C = 3;

constexpr int L = 1200;           // output chunk length; T/L = 25 chunks
constexpr int W = 336;            // warm-up steps; (L+W) = 1536 = 6*256 exactly
constexpr int NCHUNK = T / L;     // 25

constexpr float ALPHA = 0.939f;
constexpr float CFF   = 3.0f;
constexpr float EPS   = 1e-10f;

__host__ __device__ constexpr double dpow(double a, int n) {
    double v = 1.0;
    for (int i = 0; i < n; ++i) v *= a;
    return v;
}
__device__ constexpr float APJ[8] = {   // alpha^(j+1), j = 0..7
    (float)dpow(0.939, 1), (float)dpow(0.939, 2), (float)dpow(0.939, 3), (float)dpow(0.939, 4),
    (float)dpow(0.939, 5), (float)dpow(0.939, 6), (float)dpow(0.939, 7), (float)dpow(0.939, 8)
};
__device__ constexpr float SCOEF[5] = { // alpha^(8 * 2^st), st = 0..4
    (float)dpow(0.939, 8), (float)dpow(0.939, 16), (float)dpow(0.939, 32),
    (float)dpow(0.939, 64), (float)dpow(0.939, 128)
};

#define FULLMASK 0xffffffffu

// Per-warp smem tile: 32 rows x 32 words (4 KB). Row r's slot s (s=0..5, each a
// float4 = 4 words) lives at word r*32 + sigma_r(s)*4, with
//   sigma_r(s) = ((s + 6r) & 7) ^ ((r>>2) & 1)
// This is column-Latin over any 8 consecutive rows (row pattern conflict-free)
// AND maps any 8 consecutive tile-float4 indices G=6r+s to 8 distinct bank
// groups (transposed pattern conflict-free). Verified by enumeration.
constexpr int WARP_TILE_W = 32 * 32;      // words per warp tile

__device__ __forceinline__ int sigma_word(int r, int s) {
    return r * 32 + ((((s + 6 * r) & 7) ^ ((r >> 2) & 1)) << 2);
}

__global__ __launch_bounds__(128)
void char_scan_kernel(const float* __restrict__ in, float* __restrict__ out) {
    __shared__ float sm_all[4][WARP_TILE_W];

    const int gwarp = (blockIdx.x * blockDim.x + threadIdx.x) >> 5;
    const int lane  = threadIdx.x & 31;
    if (gwarp >= B * NCHUNK) return;

    float* const sm = sm_all[(threadIdx.x >> 5)];

    const int b  = gwarp / NCHUNK;
    const int k  = gwarp % NCHUNK;
    const int t0 = k * L;                  // first stored timestep
    const int ts = (k == 0) ? 0 : t0 - W;  // first scanned timestep
    const int tend = t0 + L;               // exclusive store bound

    const float* __restrict__ base  = in  + (size_t)b * T * C;
    float* __restrict__       obase = out + (size_t)b * T * C;

    // ---- hoisted swizzled smem offsets (constant per lane across rounds) ----
    // transposed pattern: float4 index G = 32q + lane -> (r = G/6, s = G%6)
    int offT[6];
    #pragma unroll
    for (int q = 0; q < 6; ++q) {
        const int G = q * 32 + lane;
        offT[q] = sigma_word(G / 6, G % 6);
    }
    // row pattern: own row r = lane, slots s = 0..5
    int offR[6];
    #pragma unroll
    for (int s = 0; s < 6; ++s) offR[s] = sigma_word(lane, s);

    // cross-round carries
    float carry_d[3] = {0.f, 0.f, 0.f};
    float carry_r[3];
    if (ts == 0) {
        carry_r[0] = 0.f; carry_r[1] = 0.f; carry_r[2] = 0.f;
    } else {
        carry_r[0] = base[(size_t)(ts - 1) * 3 + 0];
        carry_r[1] = base[(size_t)(ts - 1) * 3 + 1];
        carry_r[2] = base[(size_t)(ts - 1) * 3 + 2];
    }

    const int nrounds = (tend - ts + 255) >> 8;   // 256 timesteps per round
    const int g0lo = t0 * 3;     // store-valid float range [g0lo, g0hi)
    const int g0hi = tend * 3;

    for (int rd = 0; rd < nrounds; ++rd) {
        const int tb = ts + rd * 256;             // round base timestep (mult of 8)
        const int fb = tb * 3;                    // round base float index (16B aligned)

        // ---- 1) coalesced global load: 6 x float4, lane-contiguous ----
        float4 v[6];
        const float4* p4 = reinterpret_cast<const float4*>(base + fb);
        #pragma unroll
        for (int q = 0; q < 6; ++q) v[q] = p4[q * 32 + lane];

        // ---- 2) transposed (swizzled) write into smem ----
        #pragma unroll
        for (int q = 0; q < 6; ++q)
            *reinterpret_cast<float4*>(sm + offT[q]) = v[q];
        __syncwarp();

        // ---- 3) read own row: 24 floats = timesteps tb+8*lane..+7, ch-major ----
        float r[24];
        #pragma unroll
        for (int s = 0; s < 6; ++s) {
            float4 u = *reinterpret_cast<const float4*>(sm + offR[s]);
            r[s * 4 + 0] = u.x; r[s * 4 + 1] = u.y;
            r[s * 4 + 2] = u.z; r[s * 4 + 3] = u.w;
        }

        #pragma unroll
        for (int c = 0; c < 3; ++c) {
            float rp = __shfl_up_sync(FULLMASK, r[21 + c], 1);
            if (lane == 0) rp = carry_r[c];

            // local serial scan over 8 steps; lane 0 folds in carry_d
            float s[8];
            float u0 = (r[c] - rp) + EPS;
            s[0] = (lane == 0) ? fmaf(ALPHA, carry_d[c], u0) : u0;
            #pragma unroll
            for (int j = 1; j < 8; ++j) {
                float uj = (r[j * 3 + c] - r[(j - 1) * 3 + c]) + EPS;
                s[j] = fmaf(ALPHA, s[j - 1], uj);
            }

            // Kogge-Stone over lane aggregates, ratio alpha^8
            float p = s[7];
            #pragma unroll
            for (int st = 0; st < 5; ++st) {
                const int dlt = 1 << st;
                float tshf = __shfl_up_sync(FULLMASK, p, dlt);
                if (lane >= dlt) p = fmaf(SCOEF[st], tshf, p);
            }

            float inc = __shfl_up_sync(FULLMASK, p, 1);
            float dprev;
            if (lane == 0) { inc = 0.f; dprev = carry_d[c]; }
            else           { dprev = inc; }

            // carries for next round (must read r before overwrite below)
            carry_d[c] = __shfl_sync(FULLMASK, p, 31);
            carry_r[c] = __shfl_sync(FULLMASK, r[21 + c], 31);

            // fixup + output, overwriting r[] in place (saves registers)
            #pragma unroll
            for (int j = 0; j < 8; ++j) {
                float d    = fmaf(APJ[j], inc, s[j]);
                float diff = d - dprev;
                r[j * 3 + c] = fmaf(d, d, CFF * (diff * diff));
                dprev = d;
            }
        }

        // ---- 4) write own row back (same conflict-free row pattern) ----
        __syncwarp();   // everyone done reading smem (step 3) before overwrite
        #pragma unroll
        for (int s = 0; s < 6; ++s) {
            float4 u;
            u.x = r[s * 4 + 0]; u.y = r[s * 4 + 1];
            u.z = r[s * 4 + 2]; u.w = r[s * 4 + 3];
            *reinterpret_cast<float4*>(sm + offR[s]) = u;
        }
        __syncwarp();

        // ---- 5) transposed (swizzled) read + guarded coalesced global store ----
        float4* o4 = reinterpret_cast<float4*>(obase + fb);
        #pragma unroll
        for (int q = 0; q < 6; ++q) {
            const int gf = fb + (q * 32 + lane) * 4;   // global float index
            float4 w = *reinterpret_cast<const float4*>(sm + offT[q]);
            if (gf >= g0lo && gf < g0hi) o4[q * 32 + lane] = w;
        }
        __syncwarp();   // protect smem before next round's transposed writes
    }
}

extern "C" void kernel_launch(void* const* d_in, const int* in_sizes, int n_in,
                              void* d_out, int out_size) {
    (void)in_sizes; (void)n_in; (void)out_size;
    const float* in = (const float*)d_in[0];
    float* out = (float*)d_out;

    const int total_warps   = B * NCHUNK;          // 6400
    const int threads       = 128;                 // 4 warps / block
    const int warps_per_blk = threads / 32;
    const int blocks        = (total_warps + warps_per_blk - 1) / warps_per_blk;  // 1600

    char_scan_kernel<<<blocks, threads>>>(in, out);
}